// round 2
// baseline (speedup 1.0000x reference)
#include <cuda_runtime.h>
#include <cuda_bf16.h>
#include <math.h>

#define Bsz 8
#define Lsz 2048
#define Dsz 256
#define NPGC 4
#define NS4 4
#define EPS_T 1.1920929e-07f
#define EPS_C 1e-8f

// ---------------- scratch (static __device__, no allocs) ----------------
__device__ float g_h [Bsz*Lsz*Dsz];        // h  (B,L,D)
__device__ float g_b1[Bsz*Lsz*2*Dsz];      // xv / z / head hidden (B,L,512)
__device__ float g_b2[Bsz*Lsz*Dsz];        // gate / u_norm / q
__device__ float g_b3[Bsz*Lsz*Dsz];        // uT (B,D,L) / k
__device__ float g_b4[Bsz*Lsz*Dsz];        // yT (B,D,L)
__device__ float g_lam_r[Dsz*32], g_lam_i[Dsz*32], g_cm_r[Dsz*32], g_cm_i[Dsz*32];

__device__ __forceinline__ float gelu_f(float x) {
    return 0.5f * x * (1.f + erff(x * 0.70710678118654752f));
}

// ---------------- encoder: h = x(.,4) @ enc_w(4,256) + enc_b ----------------
__global__ void encoder_k(const float* __restrict__ x, const float* __restrict__ w,
                          const float* __restrict__ b, float* __restrict__ h) {
    long m = blockIdx.x;            // B*L rows
    int d = threadIdx.x;            // 256
    const float* xr = x + m * 4;
    float acc = b[d];
    #pragma unroll
    for (int i = 0; i < 4; i++) acc = fmaf(xr[i], w[i * 256 + d], acc);
    h[m * 256 + d] = acc;
}

// ---------------- generic strided SGEMM ----------------
// C[m,n] = act( alpha * sum_k A[m,k]*B[k,n] + bias )
#define BM 64
#define BN 64
#define BKt 16
__global__ void gemm_k(const float* __restrict__ A, const float* __restrict__ Bm,
                       const float* __restrict__ bias, float* __restrict__ C,
                       int M, int N, int K,
                       long long As_m, long long As_k, long long As_b,
                       long long Bs_k, long long Bs_n, long long Bs_b,
                       long long Cs_m, long long Cs_n, long long Cs_b,
                       float alpha, int act, int bias_mode) {
    __shared__ float As[BKt][BM + 4];
    __shared__ float Bs[BKt][BN + 4];
    int batch = blockIdx.z;
    const float* Ab = A + (long long)batch * As_b;
    const float* Bb = Bm + (long long)batch * Bs_b;
    float* Cb = C + (long long)batch * Cs_b;
    int m0 = blockIdx.y * BM, n0 = blockIdx.x * BN;
    int tid = threadIdx.x;
    int tx = tid & 15, ty = tid >> 4;
    float acc[4][4];
    #pragma unroll
    for (int i = 0; i < 4; i++)
        #pragma unroll
        for (int j = 0; j < 4; j++) acc[i][j] = 0.f;

    for (int k0 = 0; k0 < K; k0 += BKt) {
        #pragma unroll
        for (int it = 0; it < (BM * BKt) / 256; it++) {
            int i = tid + it * 256;
            int m, k;
            if (As_k == 1) { k = i % BKt; m = i / BKt; }
            else           { m = i % BM;  k = i / BM;  }
            int gm = m0 + m, gk = k0 + k;
            float v = (gm < M && gk < K) ? Ab[(long long)gm * As_m + (long long)gk * As_k] : 0.f;
            As[k][m] = v;
        }
        #pragma unroll
        for (int it = 0; it < (BN * BKt) / 256; it++) {
            int i = tid + it * 256;
            int n, k;
            if (Bs_n == 1) { n = i % BN;  k = i / BN;  }
            else           { k = i % BKt; n = i / BKt; }
            int gn = n0 + n, gk = k0 + k;
            float v = (gn < N && gk < K) ? Bb[(long long)gk * Bs_k + (long long)gn * Bs_n] : 0.f;
            Bs[k][n] = v;
        }
        __syncthreads();
        #pragma unroll
        for (int kk = 0; kk < BKt; kk++) {
            float a[4], b[4];
            #pragma unroll
            for (int i = 0; i < 4; i++) a[i] = As[kk][ty * 4 + i];
            #pragma unroll
            for (int i = 0; i < 4; i++) b[i] = Bs[kk][tx * 4 + i];
            #pragma unroll
            for (int i = 0; i < 4; i++)
                #pragma unroll
                for (int j = 0; j < 4; j++)
                    acc[i][j] = fmaf(a[i], b[j], acc[i][j]);
        }
        __syncthreads();
    }
    #pragma unroll
    for (int i = 0; i < 4; i++) {
        int gm = m0 + ty * 4 + i;
        if (gm >= M) continue;
        #pragma unroll
        for (int j = 0; j < 4; j++) {
            int gn = n0 + tx * 4 + j;
            if (gn >= N) continue;
            float v = acc[i][j] * alpha;
            if (bias_mode == 1) v += bias[gn];
            else if (bias_mode == 2) v += bias[gm];
            if (act == 1) v = gelu_f(v);
            Cb[(long long)gm * Cs_m + (long long)gn * Cs_n] = v;
        }
    }
}

// ---------------- RMSNorm over a row ----------------
__global__ void rmsnorm_k(const float* __restrict__ in, const float* __restrict__ w,
                          float* __restrict__ out, int ncols, float eps) {
    long row = blockIdx.x;
    const float* r = in + row * (long)ncols;
    float ss = 0.f;
    for (int c = threadIdx.x; c < ncols; c += blockDim.x) { float v = r[c]; ss = fmaf(v, v, ss); }
    #pragma unroll
    for (int o = 16; o; o >>= 1) ss += __shfl_xor_sync(~0u, ss, o);
    __shared__ float sh[32];
    int wid = threadIdx.x >> 5, lane = threadIdx.x & 31;
    if (lane == 0) sh[wid] = ss;
    __syncthreads();
    int nw = blockDim.x >> 5;
    if (wid == 0) {
        ss = (lane < nw) ? sh[lane] : 0.f;
        #pragma unroll
        for (int o = 16; o; o >>= 1) ss += __shfl_xor_sync(~0u, ss, o);
        if (lane == 0) sh[0] = ss;
    }
    __syncthreads();
    float scale = rsqrtf(sh[0] / (float)ncols + eps);
    for (int c = threadIdx.x; c < ncols; c += blockDim.x)
        out[row * (long)ncols + c] = r[c] * scale * w[c];
}

// ---------------- PGC conv3 + gate ----------------
__global__ void conv_gate_k(const float* __restrict__ xv, const float* __restrict__ cw,
                            const float* __restrict__ cb, float* __restrict__ g) {
    long bl = blockIdx.x;           // B*L
    int l = (int)(bl & (Lsz - 1));
    int e = threadIdx.x;            // 256
    const float* base = xv + bl * 512;
    float xm = (l > 0)       ? base[-512 + e] : 0.f;
    float xc = base[e];
    float xp = (l < Lsz - 1) ? base[ 512 + e] : 0.f;
    float v  = base[256 + e];
    float w0 = cw[e * 3], w1 = cw[e * 3 + 1], w2 = cw[e * 3 + 2];
    float conv = fmaf(w0, xm, fmaf(w1, xc, fmaf(w2, xp, cb[e])));
    g[bl * 256 + e] = v * conv;
}

// ---------------- transpose (B,L,D) -> (B,D,L) ----------------
__global__ void transpose_LD(const float* __restrict__ in, float* __restrict__ out) {
    __shared__ float tile[32][33];
    int b = blockIdx.z;
    int l0 = blockIdx.x * 32, d0 = blockIdx.y * 32;
    #pragma unroll
    for (int j = 0; j < 32; j += 8)
        tile[threadIdx.y + j][threadIdx.x] =
            in[((long)b * Lsz + (l0 + threadIdx.y + j)) * Dsz + d0 + threadIdx.x];
    __syncthreads();
    #pragma unroll
    for (int j = 0; j < 32; j += 8)
        out[((long)b * Dsz + (d0 + threadIdx.y + j)) * Lsz + l0 + threadIdx.x] =
            tile[threadIdx.x][threadIdx.y + j];
}

// ---------------- S4D parameter precompute: lambda = exp(dt*A), Cm = C*(lambda-1)/A ----------------
__global__ void s4_pre_k(const float* __restrict__ C_ri, const float* __restrict__ log_dt,
                         const float* __restrict__ logAr, const float* __restrict__ Aim,
                         float* __restrict__ lam_r, float* __restrict__ lam_i,
                         float* __restrict__ cm_r, float* __restrict__ cm_i) {
    int idx = blockIdx.x * blockDim.x + threadIdx.x;
    if (idx >= Dsz * 32) return;
    int h = idx >> 5;
    float dt = expf(log_dt[h]);
    float Ar = -expf(logAr[idx]);
    float Ai = Aim[idx];
    float dr = Ar * dt, di = Ai * dt;
    float er = expf(dr);
    float lr = er * cosf(di), li = er * sinf(di);
    lam_r[idx] = lr; lam_i[idx] = li;
    float Er = lr - 1.f, Ei = li;
    float den = Ar * Ar + Ai * Ai;
    float qr = (Er * Ar + Ei * Ai) / den;
    float qi = (Ei * Ar - Er * Ai) / den;
    float Cr = C_ri[idx * 2], Ci = C_ri[idx * 2 + 1];
    cm_r[idx] = Cr * qr - Ci * qi;
    cm_i[idx] = Cr * qi + Ci * qr;
}

// ---------------- S4D diagonal recurrence (one warp per (b,h), lanes = 32 modes) ----------------
// y[l] = gelu( 2*Re(sum_n Cm_n s_n[l]) + Dp*u[l] ),  s_n[l] = lam_n s_n[l-1] + u[l]
__global__ void s4_scan_k(const float* __restrict__ u,
                          const float* __restrict__ lam_r, const float* __restrict__ lam_i,
                          const float* __restrict__ cm_r, const float* __restrict__ cm_i,
                          const float* __restrict__ Dp, float* __restrict__ y) {
    int gw = (blockIdx.x * blockDim.x + threadIdx.x) >> 5;
    int lane = threadIdx.x & 31;
    int b = gw >> 8, h = gw & 255;
    int idx = h * 32 + lane;
    float lr = lam_r[idx], li = lam_i[idx];
    float cr = cm_r[idx],  ci = cm_i[idx];
    float dp = Dp[h];
    const float* up = u + ((long)b * Dsz + h) * Lsz;
    float*       yp = y + ((long)b * Dsz + h) * Lsz;
    float sr = 0.f, si = 0.f;
    #pragma unroll 4
    for (int l = 0; l < Lsz; l++) {
        float uv = __ldg(up + l);
        float nsr = fmaf(lr, sr, fmaf(-li, si, uv));
        float nsi = fmaf(lr, si, li * sr);
        sr = nsr; si = nsi;
        float c = cr * sr - ci * si;
        c += __shfl_xor_sync(~0u, c, 16);
        c += __shfl_xor_sync(~0u, c, 8);
        c += __shfl_xor_sync(~0u, c, 4);
        c += __shfl_xor_sync(~0u, c, 2);
        c += __shfl_xor_sync(~0u, c, 1);
        if (lane == 0) {
            float yv = fmaf(dp, uv, 2.f * c);
            yp[l] = gelu_f(yv);
        }
    }
}

// ---------------- GLU + residual: h += a*sigmoid(g), z in (B,L,512) ----------------
__global__ void glu_res_k(const float* __restrict__ z, float* __restrict__ h) {
    long idx = (long)blockIdx.x * 256 + threadIdx.x;   // B*L*256
    long row = idx >> 8;
    int o = (int)(idx & 255);
    float a = z[row * 512 + o];
    float g = z[row * 512 + 256 + o];
    h[idx] += a * (1.f / (1.f + expf(-g)));
}

// ---------------- unpaired column ----------------
__global__ void unpaired_k(const float* __restrict__ ub, float* __restrict__ out) {
    int idx = blockIdx.x * blockDim.x + threadIdx.x;   // B*L
    out[(long)idx * 2054 + 2053] = ub[0];
}

// ---------------- host ----------------
static void gemm_launch(const float* A, const float* B, const float* bias, float* C,
                        int M, int N, int K,
                        long long asm_, long long ask, long long asb,
                        long long bsk, long long bsn, long long bsb,
                        long long csm, long long csn, long long csb,
                        float alpha, int act, int bias_mode, int batch) {
    dim3 grid((N + BN - 1) / BN, (M + BM - 1) / BM, batch);
    gemm_k<<<grid, 256>>>(A, B, bias, C, M, N, K,
                          asm_, ask, asb, bsk, bsn, bsb, csm, csn, csb,
                          alpha, act, bias_mode);
}

extern "C" void kernel_launch(void* const* d_in, const int* in_sizes, int n_in,
                              void* d_out, int out_size) {
    const float* x          = (const float*)d_in[0];
    const float* enc_w      = (const float*)d_in[1];
    const float* enc_b      = (const float*)d_in[2];
    const float* pgc_in_w   = (const float*)d_in[3];
    const float* pgc_in_b   = (const float*)d_in[4];
    const float* pgc_innorm = (const float*)d_in[5];
    const float* pgc_conv_w = (const float*)d_in[6];
    const float* pgc_conv_b = (const float*)d_in[7];
    const float* pgc_norm_w = (const float*)d_in[8];
    const float* pgc_out_w  = (const float*)d_in[9];
    const float* pgc_out_b  = (const float*)d_in[10];
    const float* s4_norm_w  = (const float*)d_in[11];
    const float* s4_Dp      = (const float*)d_in[12];
    const float* s4_C       = (const float*)d_in[13];
    const float* s4_log_dt  = (const float*)d_in[14];
    const float* s4_logAr   = (const float*)d_in[15];
    const float* s4_Aim     = (const float*)d_in[16];
    const float* s4_out_w   = (const float*)d_in[17];
    const float* s4_out_b   = (const float*)d_in[18];
    const float* db_w1      = (const float*)d_in[19];
    const float* db_b1      = (const float*)d_in[20];
    const float* db_w2      = (const float*)d_in[21];
    const float* db_b2      = (const float*)d_in[22];
    const float* bin_w1     = (const float*)d_in[23];
    const float* bin_b1     = (const float*)d_in[24];
    const float* bin_w2     = (const float*)d_in[25];
    const float* bin_b2     = (const float*)d_in[26];
    const float* q_w        = (const float*)d_in[27];
    const float* q_b        = (const float*)d_in[28];
    const float* k_w        = (const float*)d_in[29];
    const float* k_b        = (const float*)d_in[30];
    const float* ub         = (const float*)d_in[31];
    float* out = (float*)d_out;

    float *h, *b1, *b2, *b3, *b4, *lr, *li, *cr, *ci;
    cudaGetSymbolAddress((void**)&h,  g_h);
    cudaGetSymbolAddress((void**)&b1, g_b1);
    cudaGetSymbolAddress((void**)&b2, g_b2);
    cudaGetSymbolAddress((void**)&b3, g_b3);
    cudaGetSymbolAddress((void**)&b4, g_b4);
    cudaGetSymbolAddress((void**)&lr, g_lam_r);
    cudaGetSymbolAddress((void**)&li, g_lam_i);
    cudaGetSymbolAddress((void**)&cr, g_cm_r);
    cudaGetSymbolAddress((void**)&ci, g_cm_i);

    const int ML = Bsz * Lsz;   // 16384

    // encoder
    encoder_k<<<ML, 256>>>(x, enc_w, enc_b, h);

    // PGC stack
    for (int i = 0; i < NPGC; i++) {
        gemm_launch(h, pgc_in_w + (long)i * 256 * 512, pgc_in_b + i * 512, b1,
                    ML, 512, 256,
                    256, 1, 0,   512, 1, 0,   512, 1, 0,
                    1.f, 0, 1, 1);
        rmsnorm_k<<<ML, 256>>>(b1, pgc_innorm + i * 512, b1, 512, EPS_T);
        conv_gate_k<<<ML, 256>>>(b1, pgc_conv_w + i * 768, pgc_conv_b + i * 256, b2);
        rmsnorm_k<<<ML, 256>>>(b2, pgc_norm_w + i * 256, b2, 256, EPS_T);
        gemm_launch(b2, pgc_out_w + (long)i * 256 * 256, pgc_out_b + i * 256, h,
                    ML, 256, 256,
                    256, 1, 0,   256, 1, 0,   256, 1, 0,
                    1.f, 0, 1, 1);
    }

    // S4D stack (prenorm residual); h stays (B,L,D)
    for (int i = 0; i < NS4; i++) {
        s4_pre_k<<<32, 256>>>(s4_C + (long)i * 256 * 32 * 2, s4_log_dt + i * 256,
                              s4_logAr + (long)i * 8192, s4_Aim + (long)i * 8192,
                              lr, li, cr, ci);
        rmsnorm_k<<<ML, 256>>>(h, s4_norm_w + i * 256, b2, 256, EPS_C);
        transpose_LD<<<dim3(Lsz / 32, Dsz / 32, Bsz), dim3(32, 8)>>>(b2, b3);
        s4_scan_k<<<(Bsz * Dsz) / 4, 128>>>(b3, lr, li, cr, ci, s4_Dp + i * 256, b4);
        // z (B,L,512) = y^T @ W^T + b :  A[m=l,k=h] = yT[h*L+l], B[k=h,n=o] = W[o*256+h]
        gemm_launch(b4, s4_out_w + (long)i * 512 * 256, s4_out_b + i * 512, b1,
                    Lsz, 512, 256,
                    1, Lsz, (long long)Dsz * Lsz,
                    1, 256, 0,
                    512, 1, (long long)Lsz * 512,
                    1.f, 0, 1, Bsz);
        glu_res_k<<<ML, 256>>>(b1, h);
    }

    // heads
    // dotbracket
    gemm_launch(h, db_w1, db_b1, b1, ML, 128, 256,
                256, 1, 0,  128, 1, 0,  128, 1, 0,  1.f, 1, 1, 1);
    gemm_launch(b1, db_w2, db_b2, out, ML, 3, 128,
                128, 1, 0,  3, 1, 0,  2054, 1, 0,  1.f, 0, 1, 1);
    // binary
    gemm_launch(h, bin_w1, bin_b1, b1, ML, 64, 256,
                256, 1, 0,  64, 1, 0,  64, 1, 0,  1.f, 1, 1, 1);
    gemm_launch(b1, bin_w2, bin_b2, out + 3, ML, 2, 64,
                64, 1, 0,  2, 1, 0,  2054, 1, 0,  1.f, 0, 1, 1);
    // q, k
    gemm_launch(h, q_w, q_b, b2, ML, 256, 256,
                256, 1, 0,  256, 1, 0,  256, 1, 0,  1.f, 0, 1, 1);
    gemm_launch(h, k_w, k_b, b3, ML, 256, 256,
                256, 1, 0,  256, 1, 0,  256, 1, 0,  1.f, 0, 1, 1);
    // scores = q @ k^T / 16  -> out[:, :, 5:5+2048]
    gemm_launch(b2, b3, nullptr, out + 5, Lsz, Lsz, 256,
                256, 1, (long long)Lsz * 256,
                1, 256, (long long)Lsz * 256,
                2054, 1, (long long)Lsz * 2054,
                0.0625f, 0, 0, Bsz);
    // unpaired bias column
    unpaired_k<<<ML / 256, 256>>>(ub, out);
}

// round 4
// speedup vs baseline: 1.1101x; 1.1101x over previous
#include <cuda_runtime.h>
#include <cuda_bf16.h>
#include <math.h>
#include <stdint.h>

#define Bsz 8
#define Lsz 2048
#define Dsz 256
#define NPGC 4
#define NS4 4
#define EPS_T 1.1920929e-07f
#define EPS_C 1e-8f

// ---------------- scratch (static __device__, no allocs) ----------------
__device__ float g_h [Bsz*Lsz*Dsz];        // h  (B,L,D)
__device__ float g_b1[Bsz*Lsz*2*Dsz];      // xv / z / head hidden (B,L,512)
__device__ float g_b2[Bsz*Lsz*Dsz];        // gate / u_norm / q
__device__ float g_b3[Bsz*Lsz*Dsz];        // uT (B,D,L) / k
__device__ float g_b4[Bsz*Lsz*Dsz];        // yT (B,D,L)
__device__ float g_lam_r[Dsz*32], g_lam_i[Dsz*32], g_cm_r[Dsz*32], g_cm_i[Dsz*32];

__device__ __forceinline__ float gelu_f(float x) {
    return 0.5f * x * (1.f + erff(x * 0.70710678118654752f));
}

__device__ __forceinline__ float to_tf32(float x) {
    uint32_t u;
    asm("cvt.rna.tf32.f32 %0, %1;" : "=r"(u) : "f"(x));
    return __uint_as_float(u);
}

__device__ __forceinline__ void mma_tf32(float* d, const uint32_t* a, const uint32_t* b) {
    asm volatile(
        "mma.sync.aligned.m16n8k8.row.col.f32.tf32.tf32.f32 "
        "{%0,%1,%2,%3},{%4,%5,%6,%7},{%8,%9},{%0,%1,%2,%3};"
        : "+f"(d[0]), "+f"(d[1]), "+f"(d[2]), "+f"(d[3])
        : "r"(a[0]), "r"(a[1]), "r"(a[2]), "r"(a[3]), "r"(b[0]), "r"(b[1]));
}

// ---------------- encoder ----------------
__global__ void encoder_k(const float* __restrict__ x, const float* __restrict__ w,
                          const float* __restrict__ b, float* __restrict__ h) {
    long m = blockIdx.x;
    int d = threadIdx.x;
    const float* xr = x + m * 4;
    float acc = b[d];
    #pragma unroll
    for (int i = 0; i < 4; i++) acc = fmaf(xr[i], w[i * 256 + d], acc);
    h[m * 256 + d] = acc;
}

// ---------------- 3xTF32 tensor-core GEMM (fp32-accurate) ----------------
#define TBM 128
#define TBN 128
#define TBK 16
__global__ __launch_bounds__(256, 2)
void gemm_tc(const float* __restrict__ A, const float* __restrict__ Bm,
             const float* __restrict__ bias, float* __restrict__ C,
             int M, int N, int K,
             long long As_m, long long As_k, long long As_b,
             long long Bs_k, long long Bs_n, long long Bs_b,
             long long Cs_m, long long Cs_n, long long Cs_b,
             float alpha, int act, int bias_mode) {
    __shared__ float Ah[TBK][TBM + 4];
    __shared__ float Al[TBK][TBM + 4];
    __shared__ float Bh[TBK][TBN + 4];
    __shared__ float Bl[TBK][TBN + 4];
    int batch = blockIdx.z;
    const float* Ab = A + (long long)batch * As_b;
    const float* Bb = Bm + (long long)batch * Bs_b;
    float* Cb = C + (long long)batch * Cs_b;
    int m0 = blockIdx.y * TBM, n0 = blockIdx.x * TBN;
    int tid = threadIdx.x;
    int w = tid >> 5, lane = tid & 31;
    int wm = (w & 1) * 64, wn = (w >> 1) * 32;
    int gid = lane >> 2, tig = lane & 3;

    float acc[4][4][4];
    #pragma unroll
    for (int i = 0; i < 4; i++)
        #pragma unroll
        for (int j = 0; j < 4; j++)
            #pragma unroll
            for (int r = 0; r < 4; r++) acc[i][j][r] = 0.f;

    for (int k0 = 0; k0 < K; k0 += TBK) {
        #pragma unroll
        for (int it = 0; it < 8; it++) {
            int i = tid + it * 256;
            int m, k;
            if (As_k == 1) { k = i & 15; m = i >> 4; }
            else           { m = i & 127; k = i >> 7; }
            int gm = m0 + m, gk = k0 + k;
            float v = (gm < M && gk < K) ? Ab[(long long)gm * As_m + (long long)gk * As_k] : 0.f;
            float hi = to_tf32(v);
            Ah[k][m] = hi;
            Al[k][m] = to_tf32(v - hi);
        }
        #pragma unroll
        for (int it = 0; it < 8; it++) {
            int i = tid + it * 256;
            int n, k;
            if (Bs_n == 1) { n = i & 127; k = i >> 7; }
            else           { k = i & 15;  n = i >> 4; }
            int gn = n0 + n, gk = k0 + k;
            float v = (gn < N && gk < K) ? Bb[(long long)gk * Bs_k + (long long)gn * Bs_n] : 0.f;
            float hi = to_tf32(v);
            Bh[k][n] = hi;
            Bl[k][n] = to_tf32(v - hi);
        }
        __syncthreads();
        #pragma unroll
        for (int kf = 0; kf < 2; kf++) {
            int kb = kf * 8;
            uint32_t bh[4][2], bl[4][2];
            #pragma unroll
            for (int nf = 0; nf < 4; nf++) {
                int nc = wn + nf * 8 + gid;
                bh[nf][0] = __float_as_uint(Bh[kb + tig    ][nc]);
                bh[nf][1] = __float_as_uint(Bh[kb + tig + 4][nc]);
                bl[nf][0] = __float_as_uint(Bl[kb + tig    ][nc]);
                bl[nf][1] = __float_as_uint(Bl[kb + tig + 4][nc]);
            }
            #pragma unroll
            for (int mf = 0; mf < 4; mf++) {
                int mr = wm + mf * 16 + gid;
                uint32_t ah[4], al[4];
                ah[0] = __float_as_uint(Ah[kb + tig    ][mr    ]);
                ah[1] = __float_as_uint(Ah[kb + tig    ][mr + 8]);
                ah[2] = __float_as_uint(Ah[kb + tig + 4][mr    ]);
                ah[3] = __float_as_uint(Ah[kb + tig + 4][mr + 8]);
                al[0] = __float_as_uint(Al[kb + tig    ][mr    ]);
                al[1] = __float_as_uint(Al[kb + tig    ][mr + 8]);
                al[2] = __float_as_uint(Al[kb + tig + 4][mr    ]);
                al[3] = __float_as_uint(Al[kb + tig + 4][mr + 8]);
                #pragma unroll
                for (int nf = 0; nf < 4; nf++) {
                    mma_tf32(acc[mf][nf], ah, bl[nf]);
                    mma_tf32(acc[mf][nf], al, bh[nf]);
                    mma_tf32(acc[mf][nf], ah, bh[nf]);
                }
            }
        }
        __syncthreads();
    }

    #pragma unroll
    for (int mf = 0; mf < 4; mf++) {
        #pragma unroll
        for (int nf = 0; nf < 4; nf++) {
            int col = n0 + wn + nf * 8 + 2 * tig;
            #pragma unroll
            for (int r = 0; r < 4; r++) {
                int row = m0 + wm + mf * 16 + gid + ((r >> 1) ? 8 : 0);
                int gn = col + (r & 1);
                if (row >= M || gn >= N) continue;
                float v = acc[mf][nf][r] * alpha;
                if (bias_mode == 1) v += bias[gn];
                if (act == 1) v = gelu_f(v);
                Cb[(long long)row * Cs_m + (long long)gn * Cs_n] = v;
            }
        }
    }
}

// ---------------- small scalar GEMM (tiny N heads) ----------------
__global__ void gemm_small(const float* __restrict__ A, const float* __restrict__ Bm,
                           const float* __restrict__ bias, float* __restrict__ C,
                           int N, int K, long long Cs_m) {
    long m = blockIdx.x;
    int tid = threadIdx.x;
    const float* Ar = A + m * K;
    __shared__ float red[4][128];
    for (int n = 0; n < N; n++) {
        float s = 0.f;
        for (int k = tid; k < K; k += 128) s = fmaf(Ar[k], Bm[(long)k * N + n], s);
        red[n][tid] = s;
    }
    __syncthreads();
    if (tid < N) {
        float s = 0.f;
        #pragma unroll
        for (int i = 0; i < 128; i++) s += red[tid][i];
        C[m * Cs_m + tid] = s + bias[tid];
    }
}

// ---------------- RMSNorm ----------------
__global__ void rmsnorm_k(const float* __restrict__ in, const float* __restrict__ w,
                          float* __restrict__ out, int ncols, float eps) {
    long row = blockIdx.x;
    const float* r = in + row * (long)ncols;
    float ss = 0.f;
    for (int c = threadIdx.x; c < ncols; c += blockDim.x) { float v = r[c]; ss = fmaf(v, v, ss); }
    #pragma unroll
    for (int o = 16; o; o >>= 1) ss += __shfl_xor_sync(~0u, ss, o);
    __shared__ float sh[32];
    int wid = threadIdx.x >> 5, lane = threadIdx.x & 31;
    if (lane == 0) sh[wid] = ss;
    __syncthreads();
    int nw = blockDim.x >> 5;
    if (wid == 0) {
        ss = (lane < nw) ? sh[lane] : 0.f;
        #pragma unroll
        for (int o = 16; o; o >>= 1) ss += __shfl_xor_sync(~0u, ss, o);
        if (lane == 0) sh[0] = ss;
    }
    __syncthreads();
    float scale = rsqrtf(sh[0] / (float)ncols + eps);
    for (int c = threadIdx.x; c < ncols; c += blockDim.x)
        out[row * (long)ncols + c] = r[c] * scale * w[c];
}

// ---------------- PGC conv3 + gate ----------------
__global__ void conv_gate_k(const float* __restrict__ xv, const float* __restrict__ cw,
                            const float* __restrict__ cb, float* __restrict__ g) {
    long bl = blockIdx.x;
    int l = (int)(bl & (Lsz - 1));
    int e = threadIdx.x;
    const float* base = xv + bl * 512;
    float xm = (l > 0)       ? base[-512 + e] : 0.f;
    float xc = base[e];
    float xp = (l < Lsz - 1) ? base[ 512 + e] : 0.f;
    float v  = base[256 + e];
    float w0 = cw[e * 3], w1 = cw[e * 3 + 1], w2 = cw[e * 3 + 2];
    float conv = fmaf(w0, xm, fmaf(w1, xc, fmaf(w2, xp, cb[e])));
    g[bl * 256 + e] = v * conv;
}

// ---------------- transpose (B,L,D) -> (B,D,L) ----------------
__global__ void transpose_LD(const float* __restrict__ in, float* __restrict__ out) {
    __shared__ float tile[32][33];
    int b = blockIdx.z;
    int l0 = blockIdx.x * 32, d0 = blockIdx.y * 32;
    #pragma unroll
    for (int j = 0; j < 32; j += 8)
        tile[threadIdx.y + j][threadIdx.x] =
            in[((long)b * Lsz + (l0 + threadIdx.y + j)) * Dsz + d0 + threadIdx.x];
    __syncthreads();
    #pragma unroll
    for (int j = 0; j < 32; j += 8)
        out[((long)b * Dsz + (d0 + threadIdx.y + j)) * Lsz + l0 + threadIdx.x] =
            tile[threadIdx.x][threadIdx.y + j];
}

// ---------------- S4D parameter precompute ----------------
__global__ void s4_pre_k(const float* __restrict__ C_ri, const float* __restrict__ log_dt,
                         const float* __restrict__ logAr, const float* __restrict__ Aim,
                         float* __restrict__ lam_r, float* __restrict__ lam_i,
                         float* __restrict__ cm_r, float* __restrict__ cm_i) {
    int idx = blockIdx.x * blockDim.x + threadIdx.x;
    if (idx >= Dsz * 32) return;
    int h = idx >> 5;
    float dt = expf(log_dt[h]);
    float Ar = -expf(logAr[idx]);
    float Ai = Aim[idx];
    float dr = Ar * dt, di = Ai * dt;
    float er = expf(dr);
    float lr = er * cosf(di), li = er * sinf(di);
    lam_r[idx] = lr; lam_i[idx] = li;
    float Er = lr - 1.f, Ei = li;
    float den = Ar * Ar + Ai * Ai;
    float qr = (Er * Ar + Ei * Ai) / den;
    float qi = (Ei * Ar - Er * Ai) / den;
    float Cr = C_ri[idx * 2], Ci = C_ri[idx * 2 + 1];
    cm_r[idx] = Cr * qr - Ci * qi;
    cm_i[idx] = Cr * qi + Ci * qr;
}

// ---------------- S4D diagonal recurrence (one warp per (b,h)) ----------------
__global__ void s4_scan_k(const float* __restrict__ u,
                          const float* __restrict__ lam_r, const float* __restrict__ lam_i,
                          const float* __restrict__ cm_r, const float* __restrict__ cm_i,
                          const float* __restrict__ Dp, float* __restrict__ y) {
    int gw = (blockIdx.x * blockDim.x + threadIdx.x) >> 5;
    int lane = threadIdx.x & 31;
    int b = gw >> 8, h = gw & 255;
    int idx = h * 32 + lane;
    float lr = lam_r[idx], li = lam_i[idx];
    float cr = cm_r[idx],  ci = cm_i[idx];
    float dp = Dp[h];
    const float* up = u + ((long)b * Dsz + h) * Lsz;
    float*       yp = y + ((long)b * Dsz + h) * Lsz;
    float sr = 0.f, si = 0.f;
    #pragma unroll 4
    for (int l = 0; l < Lsz; l++) {
        float uv = __ldg(up + l);
        float nsr = fmaf(lr, sr, fmaf(-li, si, uv));
        float nsi = fmaf(lr, si, li * sr);
        sr = nsr; si = nsi;
        float c = cr * sr - ci * si;
        c += __shfl_xor_sync(~0u, c, 16);
        c += __shfl_xor_sync(~0u, c, 8);
        c += __shfl_xor_sync(~0u, c, 4);
        c += __shfl_xor_sync(~0u, c, 2);
        c += __shfl_xor_sync(~0u, c, 1);
        if (lane == 0) {
            float yv = fmaf(dp, uv, 2.f * c);
            yp[l] = gelu_f(yv);
        }
    }
}

// ---------------- GLU + residual ----------------
__global__ void glu_res_k(const float* __restrict__ z, float* __restrict__ h) {
    long idx = (long)blockIdx.x * 256 + threadIdx.x;
    long row = idx >> 8;
    int o = (int)(idx & 255);
    float a = z[row * 512 + o];
    float g = z[row * 512 + 256 + o];
    h[idx] += a * (1.f / (1.f + expf(-g)));
}

// ---------------- unpaired column ----------------
__global__ void unpaired_k(const float* __restrict__ ub, float* __restrict__ out) {
    int idx = blockIdx.x * blockDim.x + threadIdx.x;
    out[(long)idx * 2054 + 2053] = ub[0];
}

// ---------------- host ----------------
static void gemm_launch(const float* A, const float* B, const float* bias, float* C,
                        int M, int N, int K,
                        long long asm_, long long ask, long long asb,
                        long long bsk, long long bsn, long long bsb,
                        long long csm, long long csn, long long csb,
                        float alpha, int act, int bias_mode, int batch) {
    dim3 grid((N + TBN - 1) / TBN, (M + TBM - 1) / TBM, batch);
    gemm_tc<<<grid, 256>>>(A, B, bias, C, M, N, K,
                           asm_, ask, asb, bsk, bsn, bsb, csm, csn, csb,
                           alpha, act, bias_mode);
}

extern "C" void kernel_launch(void* const* d_in, const int* in_sizes, int n_in,
                              void* d_out, int out_size) {
    const float* x          = (const float*)d_in[0];
    const float* enc_w      = (const float*)d_in[1];
    const float* enc_b      = (const float*)d_in[2];
    const float* pgc_in_w   = (const float*)d_in[3];
    const float* pgc_in_b   = (const float*)d_in[4];
    const float* pgc_innorm = (const float*)d_in[5];
    const float* pgc_conv_w = (const float*)d_in[6];
    const float* pgc_conv_b = (const float*)d_in[7];
    const float* pgc_norm_w = (const float*)d_in[8];
    const float* pgc_out_w  = (const float*)d_in[9];
    const float* pgc_out_b  = (const float*)d_in[10];
    const float* s4_norm_w  = (const float*)d_in[11];
    const float* s4_Dp      = (const float*)d_in[12];
    const float* s4_C       = (const float*)d_in[13];
    const float* s4_log_dt  = (const float*)d_in[14];
    const float* s4_logAr   = (const float*)d_in[15];
    const float* s4_Aim     = (const float*)d_in[16];
    const float* s4_out_w   = (const float*)d_in[17];
    const float* s4_out_b   = (const float*)d_in[18];
    const float* db_w1      = (const float*)d_in[19];
    const float* db_b1      = (const float*)d_in[20];
    const float* db_w2      = (const float*)d_in[21];
    const float* db_b2      = (const float*)d_in[22];
    const float* bin_w1     = (const float*)d_in[23];
    const float* bin_b1     = (const float*)d_in[24];
    const float* bin_w2     = (const float*)d_in[25];
    const float* bin_b2     = (const float*)d_in[26];
    const float* q_w        = (const float*)d_in[27];
    const float* q_b        = (const float*)d_in[28];
    const float* k_w        = (const float*)d_in[29];
    const float* k_b        = (const float*)d_in[30];
    const float* ub         = (const float*)d_in[31];
    float* out = (float*)d_out;

    float *h, *b1, *b2, *b3, *b4, *lr, *li, *cr, *ci;
    cudaGetSymbolAddress((void**)&h,  g_h);
    cudaGetSymbolAddress((void**)&b1, g_b1);
    cudaGetSymbolAddress((void**)&b2, g_b2);
    cudaGetSymbolAddress((void**)&b3, g_b3);
    cudaGetSymbolAddress((void**)&b4, g_b4);
    cudaGetSymbolAddress((void**)&lr, g_lam_r);
    cudaGetSymbolAddress((void**)&li, g_lam_i);
    cudaGetSymbolAddress((void**)&cr, g_cm_r);
    cudaGetSymbolAddress((void**)&ci, g_cm_i);

    const int ML = Bsz * Lsz;   // 16384

    encoder_k<<<ML, 256>>>(x, enc_w, enc_b, h);

    for (int i = 0; i < NPGC; i++) {
        gemm_launch(h, pgc_in_w + (long)i * 256 * 512, pgc_in_b + i * 512, b1,
                    ML, 512, 256,
                    256, 1, 0,   512, 1, 0,   512, 1, 0,
                    1.f, 0, 1, 1);
        rmsnorm_k<<<ML, 256>>>(b1, pgc_innorm + i * 512, b1, 512, EPS_T);
        conv_gate_k<<<ML, 256>>>(b1, pgc_conv_w + i * 768, pgc_conv_b + i * 256, b2);
        rmsnorm_k<<<ML, 256>>>(b2, pgc_norm_w + i * 256, b2, 256, EPS_T);
        gemm_launch(b2, pgc_out_w + (long)i * 256 * 256, pgc_out_b + i * 256, h,
                    ML, 256, 256,
                    256, 1, 0,   256, 1, 0,   256, 1, 0,
                    1.f, 0, 1, 1);
    }

    for (int i = 0; i < NS4; i++) {
        s4_pre_k<<<32, 256>>>(s4_C + (long)i * 256 * 32 * 2, s4_log_dt + i * 256,
                              s4_logAr + (long)i * 8192, s4_Aim + (long)i * 8192,
                              lr, li, cr, ci);
        rmsnorm_k<<<ML, 256>>>(h, s4_norm_w + i * 256, b2, 256, EPS_C);
        transpose_LD<<<dim3(Lsz / 32, Dsz / 32, Bsz), dim3(32, 8)>>>(b2, b3);
        s4_scan_k<<<(Bsz * Dsz) / 4, 128>>>(b3, lr, li, cr, ci, s4_Dp + i * 256, b4);
        gemm_launch(b4, s4_out_w + (long)i * 512 * 256, s4_out_b + i * 512, b1,
                    Lsz, 512, 256,
                    1, Lsz, (long long)Dsz * Lsz,
                    1, 256, 0,
                    512, 1, (long long)Lsz * 512,
                    1.f, 0, 1, Bsz);
        glu_res_k<<<ML, 256>>>(b1, h);
    }

    gemm_launch(h, db_w1, db_b1, b1, ML, 128, 256,
                256, 1, 0,  128, 1, 0,  128, 1, 0,  1.f, 1, 1, 1);
    gemm_small<<<ML, 128>>>(b1, db_w2, db_b2, out, 3, 128, 2054);
    gemm_launch(h, bin_w1, bin_b1, b1, ML, 64, 256,
                256, 1, 0,  64, 1, 0,  64, 1, 0,  1.f, 1, 1, 1);
    gemm_small<<<ML, 128>>>(b1, bin_w2, bin_b2, out + 3, 2, 64, 2054);
    gemm_launch(h, q_w, q_b, b2, ML, 256, 256,
                256, 1, 0,  256, 1, 0,  256, 1, 0,  1.f, 0, 1, 1);
    gemm_launch(h, k_w, k_b, b3, ML, 256, 256,
                256, 1, 0,  256, 1, 0,  256, 1, 0,  1.f, 0, 1, 1);
    gemm_launch(b2, b3, nullptr, out + 5, Lsz, Lsz, 256,
                256, 1, (long long)Lsz * 256,
                1, 256, (long long)Lsz * 256,
                2054, 1, (long long)Lsz * 2054,
                0.0625f, 0, 0, Bsz);
    unpaired_k<<<ML / 256, 256>>>(ub, out);
}

// round 5
// speedup vs baseline: 1.3671x; 1.2314x over previous
#include <cuda_runtime.h>
#include <cuda_bf16.h>
#include <math.h>
#include <stdint.h>

#define Bsz 8
#define Lsz 2048
#define Dsz 256
#define NPGC 4
#define NS4 4
#define EPS_T 1.1920929e-07f
#define EPS_C 1e-8f

// ---------------- scratch (static __device__, no allocs) ----------------
__device__ float g_h [Bsz*Lsz*Dsz];
__device__ float g_b1[Bsz*Lsz*2*Dsz];
__device__ float g_b2[Bsz*Lsz*Dsz];
__device__ float g_b3[Bsz*Lsz*Dsz];
__device__ float g_b4[Bsz*Lsz*Dsz];
__device__ float g_lam_r[Dsz*32], g_lam_i[Dsz*32], g_cm_r[Dsz*32], g_cm_i[Dsz*32];

__device__ __forceinline__ float gelu_f(float x) {
    return 0.5f * x * (1.f + erff(x * 0.70710678118654752f));
}

__device__ __forceinline__ void mma_bf16(float* d, const uint32_t* a, const uint32_t* b) {
    asm volatile(
        "mma.sync.aligned.m16n8k16.row.col.f32.bf16.bf16.f32 "
        "{%0,%1,%2,%3},{%4,%5,%6,%7},{%8,%9},{%0,%1,%2,%3};"
        : "+f"(d[0]), "+f"(d[1]), "+f"(d[2]), "+f"(d[3])
        : "r"(a[0]), "r"(a[1]), "r"(a[2]), "r"(a[3]), "r"(b[0]), "r"(b[1]));
}

// ---------------- encoder ----------------
__global__ void encoder_k(const float* __restrict__ x, const float* __restrict__ w,
                          const float* __restrict__ b, float* __restrict__ h) {
    long m = blockIdx.x;
    int d = threadIdx.x;
    const float* xr = x + m * 4;
    float acc = b[d];
    #pragma unroll
    for (int i = 0; i < 4; i++) acc = fmaf(xr[i], w[i * 256 + d], acc);
    h[m * 256 + d] = acc;
}

// ---------------- bf16 3-term split tensor-core GEMM (fp32-class accuracy) ----------------
#define TBM 128
#define TBN 128
#define TBK 16
#define KP 24   // padded k-stride (48B rows -> conflict-free fragment loads)
__global__ __launch_bounds__(256, 2)
void gemm_tc(const float* __restrict__ A, const float* __restrict__ Bm,
             const float* __restrict__ bias, float* __restrict__ C,
             int M, int N, int K,
             long long As_m, long long As_k, long long As_b,
             long long Bs_k, long long Bs_n, long long Bs_b,
             long long Cs_m, long long Cs_n, long long Cs_b,
             float alpha, int act, int bias_mode) {
    __shared__ __nv_bfloat16 Ah[TBM][KP], Al[TBM][KP];
    __shared__ __nv_bfloat16 Bh[TBN][KP], Bl[TBN][KP];
    int batch = blockIdx.z;
    const float* Ab = A + (long long)batch * As_b;
    const float* Bb = Bm + (long long)batch * Bs_b;
    float* Cb = C + (long long)batch * Cs_b;
    int m0 = blockIdx.y * TBM, n0 = blockIdx.x * TBN;
    int tid = threadIdx.x;
    int w = tid >> 5, lane = tid & 31;
    int wm = (w & 1) * 64, wn = (w >> 1) * 32;
    int gid = lane >> 2, tig = lane & 3;

    float acc[4][4][4];
    #pragma unroll
    for (int i = 0; i < 4; i++)
        #pragma unroll
        for (int j = 0; j < 4; j++)
            #pragma unroll
            for (int r = 0; r < 4; r++) acc[i][j][r] = 0.f;

    float pa[8], pb[8];
    // prefetch k-tile 0 into regs
    #pragma unroll
    for (int it = 0; it < 8; it++) {
        int i = tid + it * 256;
        int m, k;
        if (As_k == 1) { k = i & 15; m = i >> 4; }
        else           { m = i & 127; k = i >> 7; }
        int gm = m0 + m, gk = k;
        pa[it] = (gm < M && gk < K) ? Ab[(long long)gm * As_m + (long long)gk * As_k] : 0.f;
    }
    #pragma unroll
    for (int it = 0; it < 8; it++) {
        int i = tid + it * 256;
        int n, k;
        if (Bs_n == 1) { n = i & 127; k = i >> 7; }
        else           { k = i & 15;  n = i >> 4; }
        int gn = n0 + n, gk = k;
        pb[it] = (gn < N && gk < K) ? Bb[(long long)gk * Bs_k + (long long)gn * Bs_n] : 0.f;
    }

    for (int k0 = 0; k0 < K; k0 += TBK) {
        // stage regs -> smem with bf16 split
        #pragma unroll
        for (int it = 0; it < 8; it++) {
            int i = tid + it * 256;
            int m, k;
            if (As_k == 1) { k = i & 15; m = i >> 4; }
            else           { m = i & 127; k = i >> 7; }
            float v = pa[it];
            __nv_bfloat16 hi = __float2bfloat16_rn(v);
            Ah[m][k] = hi;
            Al[m][k] = __float2bfloat16_rn(v - __bfloat162float(hi));
        }
        #pragma unroll
        for (int it = 0; it < 8; it++) {
            int i = tid + it * 256;
            int n, k;
            if (Bs_n == 1) { n = i & 127; k = i >> 7; }
            else           { k = i & 15;  n = i >> 4; }
            float v = pb[it];
            __nv_bfloat16 hi = __float2bfloat16_rn(v);
            Bh[n][k] = hi;
            Bl[n][k] = __float2bfloat16_rn(v - __bfloat162float(hi));
        }
        __syncthreads();

        // prefetch next k-tile
        if (k0 + TBK < K) {
            #pragma unroll
            for (int it = 0; it < 8; it++) {
                int i = tid + it * 256;
                int m, k;
                if (As_k == 1) { k = i & 15; m = i >> 4; }
                else           { m = i & 127; k = i >> 7; }
                int gm = m0 + m, gk = k0 + TBK + k;
                pa[it] = (gm < M && gk < K) ? Ab[(long long)gm * As_m + (long long)gk * As_k] : 0.f;
            }
            #pragma unroll
            for (int it = 0; it < 8; it++) {
                int i = tid + it * 256;
                int n, k;
                if (Bs_n == 1) { n = i & 127; k = i >> 7; }
                else           { k = i & 15;  n = i >> 4; }
                int gn = n0 + n, gk = k0 + TBK + k;
                pb[it] = (gn < N && gk < K) ? Bb[(long long)gk * Bs_k + (long long)gn * Bs_n] : 0.f;
            }
        }

        // compute
        uint32_t bhf[4][2], blf[4][2];
        #pragma unroll
        for (int nf = 0; nf < 4; nf++) {
            int nc = wn + nf * 8 + gid;
            bhf[nf][0] = *(const uint32_t*)&Bh[nc][2 * tig];
            bhf[nf][1] = *(const uint32_t*)&Bh[nc][2 * tig + 8];
            blf[nf][0] = *(const uint32_t*)&Bl[nc][2 * tig];
            blf[nf][1] = *(const uint32_t*)&Bl[nc][2 * tig + 8];
        }
        #pragma unroll
        for (int mf = 0; mf < 4; mf++) {
            int mr = wm + mf * 16 + gid;
            uint32_t ah[4], al[4];
            ah[0] = *(const uint32_t*)&Ah[mr    ][2 * tig];
            ah[1] = *(const uint32_t*)&Ah[mr + 8][2 * tig];
            ah[2] = *(const uint32_t*)&Ah[mr    ][2 * tig + 8];
            ah[3] = *(const uint32_t*)&Ah[mr + 8][2 * tig + 8];
            al[0] = *(const uint32_t*)&Al[mr    ][2 * tig];
            al[1] = *(const uint32_t*)&Al[mr + 8][2 * tig];
            al[2] = *(const uint32_t*)&Al[mr    ][2 * tig + 8];
            al[3] = *(const uint32_t*)&Al[mr + 8][2 * tig + 8];
            #pragma unroll
            for (int nf = 0; nf < 4; nf++) {
                mma_bf16(acc[mf][nf], ah, blf[nf]);
                mma_bf16(acc[mf][nf], al, bhf[nf]);
                mma_bf16(acc[mf][nf], ah, bhf[nf]);
            }
        }
        __syncthreads();
    }

    #pragma unroll
    for (int mf = 0; mf < 4; mf++) {
        #pragma unroll
        for (int nf = 0; nf < 4; nf++) {
            int col = n0 + wn + nf * 8 + 2 * tig;
            #pragma unroll
            for (int r = 0; r < 4; r++) {
                int row = m0 + wm + mf * 16 + gid + ((r >> 1) ? 8 : 0);
                int gn = col + (r & 1);
                if (row >= M || gn >= N) continue;
                float v = acc[mf][nf][r] * alpha;
                if (bias_mode == 1) v += bias[gn];
                if (act == 1) v = gelu_f(v);
                Cb[(long long)row * Cs_m + (long long)gn * Cs_n] = v;
            }
        }
    }
}

// ---------------- small scalar GEMM (tiny N heads) ----------------
__global__ void gemm_small(const float* __restrict__ A, const float* __restrict__ Bm,
                           const float* __restrict__ bias, float* __restrict__ C,
                           int N, int K, long long Cs_m) {
    long m = blockIdx.x;
    int tid = threadIdx.x;
    const float* Ar = A + m * K;
    __shared__ float red[4][128];
    for (int n = 0; n < N; n++) {
        float s = 0.f;
        for (int k = tid; k < K; k += 128) s = fmaf(Ar[k], Bm[(long)k * N + n], s);
        red[n][tid] = s;
    }
    __syncthreads();
    if (tid < N) {
        float s = 0.f;
        #pragma unroll
        for (int i = 0; i < 128; i++) s += red[tid][i];
        C[m * Cs_m + tid] = s + bias[tid];
    }
}

// ---------------- RMSNorm ----------------
__global__ void rmsnorm_k(const float* __restrict__ in, const float* __restrict__ w,
                          float* __restrict__ out, int ncols, float eps) {
    long row = blockIdx.x;
    const float* r = in + row * (long)ncols;
    float ss = 0.f;
    for (int c = threadIdx.x; c < ncols; c += blockDim.x) { float v = r[c]; ss = fmaf(v, v, ss); }
    #pragma unroll
    for (int o = 16; o; o >>= 1) ss += __shfl_xor_sync(~0u, ss, o);
    __shared__ float sh[32];
    int wid = threadIdx.x >> 5, lane = threadIdx.x & 31;
    if (lane == 0) sh[wid] = ss;
    __syncthreads();
    int nw = blockDim.x >> 5;
    if (wid == 0) {
        ss = (lane < nw) ? sh[lane] : 0.f;
        #pragma unroll
        for (int o = 16; o; o >>= 1) ss += __shfl_xor_sync(~0u, ss, o);
        if (lane == 0) sh[0] = ss;
    }
    __syncthreads();
    float scale = rsqrtf(sh[0] / (float)ncols + eps);
    for (int c = threadIdx.x; c < ncols; c += blockDim.x)
        out[row * (long)ncols + c] = r[c] * scale * w[c];
}

// ---------------- PGC conv3 + gate ----------------
__global__ void conv_gate_k(const float* __restrict__ xv, const float* __restrict__ cw,
                            const float* __restrict__ cb, float* __restrict__ g) {
    long bl = blockIdx.x;
    int l = (int)(bl & (Lsz - 1));
    int e = threadIdx.x;
    const float* base = xv + bl * 512;
    float xm = (l > 0)       ? base[-512 + e] : 0.f;
    float xc = base[e];
    float xp = (l < Lsz - 1) ? base[ 512 + e] : 0.f;
    float v  = base[256 + e];
    float w0 = cw[e * 3], w1 = cw[e * 3 + 1], w2 = cw[e * 3 + 2];
    float conv = fmaf(w0, xm, fmaf(w1, xc, fmaf(w2, xp, cb[e])));
    g[bl * 256 + e] = v * conv;
}

// ---------------- transpose (B,L,D) -> (B,D,L) ----------------
__global__ void transpose_LD(const float* __restrict__ in, float* __restrict__ out) {
    __shared__ float tile[32][33];
    int b = blockIdx.z;
    int l0 = blockIdx.x * 32, d0 = blockIdx.y * 32;
    #pragma unroll
    for (int j = 0; j < 32; j += 8)
        tile[threadIdx.y + j][threadIdx.x] =
            in[((long)b * Lsz + (l0 + threadIdx.y + j)) * Dsz + d0 + threadIdx.x];
    __syncthreads();
    #pragma unroll
    for (int j = 0; j < 32; j += 8)
        out[((long)b * Dsz + (d0 + threadIdx.y + j)) * Lsz + l0 + threadIdx.x] =
            tile[threadIdx.x][threadIdx.y + j];
}

// ---------------- S4D parameter precompute ----------------
__global__ void s4_pre_k(const float* __restrict__ C_ri, const float* __restrict__ log_dt,
                         const float* __restrict__ logAr, const float* __restrict__ Aim,
                         float* __restrict__ lam_r, float* __restrict__ lam_i,
                         float* __restrict__ cm_r, float* __restrict__ cm_i) {
    int idx = blockIdx.x * blockDim.x + threadIdx.x;
    if (idx >= Dsz * 32) return;
    int h = idx >> 5;
    float dt = expf(log_dt[h]);
    float Ar = -expf(logAr[idx]);
    float Ai = Aim[idx];
    float dr = Ar * dt, di = Ai * dt;
    float er = expf(dr);
    float lr = er * cosf(di), li = er * sinf(di);
    lam_r[idx] = lr; lam_i[idx] = li;
    float Er = lr - 1.f, Ei = li;
    float den = Ar * Ar + Ai * Ai;
    float qr = (Er * Ar + Ei * Ai) / den;
    float qi = (Ei * Ar - Er * Ai) / den;
    float Cr = C_ri[idx * 2], Ci = C_ri[idx * 2 + 1];
    cm_r[idx] = Cr * qr - Ci * qi;
    cm_i[idx] = Cr * qi + Ci * qr;
}

// ---------------- S4D diagonal recurrence (one warp per (b,h)) ----------------
__global__ void s4_scan_k(const float* __restrict__ u,
                          const float* __restrict__ lam_r, const float* __restrict__ lam_i,
                          const float* __restrict__ cm_r, const float* __restrict__ cm_i,
                          const float* __restrict__ Dp, float* __restrict__ y) {
    int gw = (blockIdx.x * blockDim.x + threadIdx.x) >> 5;
    int lane = threadIdx.x & 31;
    int b = gw >> 8, h = gw & 255;
    int idx = h * 32 + lane;
    float lr = lam_r[idx], li = lam_i[idx];
    float cr = cm_r[idx],  ci = cm_i[idx];
    float dp = Dp[h];
    const float* up = u + ((long)b * Dsz + h) * Lsz;
    float*       yp = y + ((long)b * Dsz + h) * Lsz;
    float sr = 0.f, si = 0.f;
    #pragma unroll 4
    for (int l = 0; l < Lsz; l++) {
        float uv = __ldg(up + l);
        float nsr = fmaf(lr, sr, fmaf(-li, si, uv));
        float nsi = fmaf(lr, si, li * sr);
        sr = nsr; si = nsi;
        float c = cr * sr - ci * si;
        c += __shfl_xor_sync(~0u, c, 16);
        c += __shfl_xor_sync(~0u, c, 8);
        c += __shfl_xor_sync(~0u, c, 4);
        c += __shfl_xor_sync(~0u, c, 2);
        c += __shfl_xor_sync(~0u, c, 1);
        if (lane == 0) {
            float yv = fmaf(dp, uv, 2.f * c);
            yp[l] = gelu_f(yv);
        }
    }
}

// ---------------- GLU + residual ----------------
__global__ void glu_res_k(const float* __restrict__ z, float* __restrict__ h) {
    long idx = (long)blockIdx.x * 256 + threadIdx.x;
    long row = idx >> 8;
    int o = (int)(idx & 255);
    float a = z[row * 512 + o];
    float g = z[row * 512 + 256 + o];
    h[idx] += a * (1.f / (1.f + expf(-g)));
}

// ---------------- unpaired column ----------------
__global__ void unpaired_k(const float* __restrict__ ub, float* __restrict__ out) {
    int idx = blockIdx.x * blockDim.x + threadIdx.x;
    out[(long)idx * 2054 + 2053] = ub[0];
}

// ---------------- host ----------------
static void gemm_launch(const float* A, const float* B, const float* bias, float* C,
                        int M, int N, int K,
                        long long asm_, long long ask, long long asb,
                        long long bsk, long long bsn, long long bsb,
                        long long csm, long long csn, long long csb,
                        float alpha, int act, int bias_mode, int batch) {
    dim3 grid((N + TBN - 1) / TBN, (M + TBM - 1) / TBM, batch);
    gemm_tc<<<grid, 256>>>(A, B, bias, C, M, N, K,
                           asm_, ask, asb, bsk, bsn, bsb, csm, csn, csb,
                           alpha, act, bias_mode);
}

extern "C" void kernel_launch(void* const* d_in, const int* in_sizes, int n_in,
                              void* d_out, int out_size) {
    const float* x          = (const float*)d_in[0];
    const float* enc_w      = (const float*)d_in[1];
    const float* enc_b      = (const float*)d_in[2];
    const float* pgc_in_w   = (const float*)d_in[3];
    const float* pgc_in_b   = (const float*)d_in[4];
    const float* pgc_innorm = (const float*)d_in[5];
    const float* pgc_conv_w = (const float*)d_in[6];
    const float* pgc_conv_b = (const float*)d_in[7];
    const float* pgc_norm_w = (const float*)d_in[8];
    const float* pgc_out_w  = (const float*)d_in[9];
    const float* pgc_out_b  = (const float*)d_in[10];
    const float* s4_norm_w  = (const float*)d_in[11];
    const float* s4_Dp      = (const float*)d_in[12];
    const float* s4_C       = (const float*)d_in[13];
    const float* s4_log_dt  = (const float*)d_in[14];
    const float* s4_logAr   = (const float*)d_in[15];
    const float* s4_Aim     = (const float*)d_in[16];
    const float* s4_out_w   = (const float*)d_in[17];
    const float* s4_out_b   = (const float*)d_in[18];
    const float* db_w1      = (const float*)d_in[19];
    const float* db_b1      = (const float*)d_in[20];
    const float* db_w2      = (const float*)d_in[21];
    const float* db_b2      = (const float*)d_in[22];
    const float* bin_w1     = (const float*)d_in[23];
    const float* bin_b1     = (const float*)d_in[24];
    const float* bin_w2     = (const float*)d_in[25];
    const float* bin_b2     = (const float*)d_in[26];
    const float* q_w        = (const float*)d_in[27];
    const float* q_b        = (const float*)d_in[28];
    const float* k_w        = (const float*)d_in[29];
    const float* k_b        = (const float*)d_in[30];
    const float* ub         = (const float*)d_in[31];
    float* out = (float*)d_out;

    float *h, *b1, *b2, *b3, *b4, *lr, *li, *cr, *ci;
    cudaGetSymbolAddress((void**)&h,  g_h);
    cudaGetSymbolAddress((void**)&b1, g_b1);
    cudaGetSymbolAddress((void**)&b2, g_b2);
    cudaGetSymbolAddress((void**)&b3, g_b3);
    cudaGetSymbolAddress((void**)&b4, g_b4);
    cudaGetSymbolAddress((void**)&lr, g_lam_r);
    cudaGetSymbolAddress((void**)&li, g_lam_i);
    cudaGetSymbolAddress((void**)&cr, g_cm_r);
    cudaGetSymbolAddress((void**)&ci, g_cm_i);

    const int ML = Bsz * Lsz;   // 16384

    encoder_k<<<ML, 256>>>(x, enc_w, enc_b, h);

    for (int i = 0; i < NPGC; i++) {
        gemm_launch(h, pgc_in_w + (long)i * 256 * 512, pgc_in_b + i * 512, b1,
                    ML, 512, 256,
                    256, 1, 0,   512, 1, 0,   512, 1, 0,
                    1.f, 0, 1, 1);
        rmsnorm_k<<<ML, 256>>>(b1, pgc_innorm + i * 512, b1, 512, EPS_T);
        conv_gate_k<<<ML, 256>>>(b1, pgc_conv_w + i * 768, pgc_conv_b + i * 256, b2);
        rmsnorm_k<<<ML, 256>>>(b2, pgc_norm_w + i * 256, b2, 256, EPS_T);
        gemm_launch(b2, pgc_out_w + (long)i * 256 * 256, pgc_out_b + i * 256, h,
                    ML, 256, 256,
                    256, 1, 0,   256, 1, 0,   256, 1, 0,
                    1.f, 0, 1, 1);
    }

    for (int i = 0; i < NS4; i++) {
        s4_pre_k<<<32, 256>>>(s4_C + (long)i * 256 * 32 * 2, s4_log_dt + i * 256,
                              s4_logAr + (long)i * 8192, s4_Aim + (long)i * 8192,
                              lr, li, cr, ci);
        rmsnorm_k<<<ML, 256>>>(h, s4_norm_w + i * 256, b2, 256, EPS_C);
        transpose_LD<<<dim3(Lsz / 32, Dsz / 32, Bsz), dim3(32, 8)>>>(b2, b3);
        s4_scan_k<<<(Bsz * Dsz) / 4, 128>>>(b3, lr, li, cr, ci, s4_Dp + i * 256, b4);
        gemm_launch(b4, s4_out_w + (long)i * 512 * 256, s4_out_b + i * 512, b1,
                    Lsz, 512, 256,
                    1, Lsz, (long long)Dsz * Lsz,
                    1, 256, 0,
                    512, 1, (long long)Lsz * 512,
                    1.f, 0, 1, Bsz);
        glu_res_k<<<ML, 256>>>(b1, h);
    }

    gemm_launch(h, db_w1, db_b1, b1, ML, 128, 256,
                256, 1, 0,  128, 1, 0,  128, 1, 0,  1.f, 1, 1, 1);
    gemm_small<<<ML, 128>>>(b1, db_w2, db_b2, out, 3, 128, 2054);
    gemm_launch(h, bin_w1, bin_b1, b1, ML, 64, 256,
                256, 1, 0,  64, 1, 0,  64, 1, 0,  1.f, 1, 1, 1);
    gemm_small<<<ML, 128>>>(b1, bin_w2, bin_b2, out + 3, 2, 64, 2054);
    gemm_launch(h, q_w, q_b, b2, ML, 256, 256,
                256, 1, 0,  256, 1, 0,  256, 1, 0,  1.f, 0, 1, 1);
    gemm_launch(h, k_w, k_b, b3, ML, 256, 256,
                256, 1, 0,  256, 1, 0,  256, 1, 0,  1.f, 0, 1, 1);
    gemm_launch(b2, b3, nullptr, out + 5, Lsz, Lsz, 256,
                256, 1, (long long)Lsz * 256,
                1, 256, (long long)Lsz * 256,
                2054, 1, (long long)Lsz * 2054,
                0.0625f, 0, 0, Bsz);
    unpaired_k<<<ML / 256, 256>>>(ub, out);
}